// round 5
// baseline (speedup 1.0000x reference)
#include <cuda_runtime.h>

// pose3d_future loss — double-buffered cp.async, TILE=64, 2 lanes/sample,
// 4 blocks/SM (16 warps) so prefetch of tile t+1 overlaps compute of tile t.
// P: [B,3,21] f32, E: [B,2,21] f32, bl: [20], R: [3,3], C: [3,1], conn: [20,2] i64

#define NJ 21
#define NB 20
#define TILE 64
#define THREADS 128
#define MAXBLK 1024

#define POSE_F 63
#define EST_F  42
#define POSE_B (POSE_F * 4)                 // 252
#define EST_B  (EST_F * 4)                  // 168
#define TILE_POSE_F (TILE * POSE_F)         // 4032
#define TILE_EST_F  (TILE * EST_F)          // 2688
#define BUF_F (TILE_POSE_F + TILE_EST_F)    // 6720 floats = 26880 B
#define SM_BL   (2 * BUF_F)
#define SM_CONN (SM_BL + NB)
#define SM_FLOATS (SM_CONN + 2 * NB)
#define SMEM_BYTES (SM_FLOATS * 4)          // ~54 KB -> 4 blocks/SM

__device__ double g_partP[MAXBLK];
__device__ double g_partB[MAXBLK];
__device__ unsigned int g_ticket;

__device__ __forceinline__ void cp16(unsigned int dst, const void* src, int nbytes) {
    asm volatile("cp.async.cg.shared.global [%0], [%1], 16, %2;\n"
                 :: "r"(dst), "l"(src), "r"(nbytes));
}
__device__ __forceinline__ void cp_commit() {
    asm volatile("cp.async.commit_group;\n");
}
__device__ __forceinline__ void cp_wait1() {
    asm volatile("cp.async.wait_group 1;\n");
}
__device__ __forceinline__ void cp_wait0() {
    asm volatile("cp.async.wait_group 0;\n");
}

__global__ __launch_bounds__(THREADS) void k_loss(
    const float* __restrict__ pose,
    const float* __restrict__ est,
    const float* __restrict__ bl,
    const float* __restrict__ R,
    const float* __restrict__ C,
    const long long* __restrict__ conn,
    float* __restrict__ out,
    int n, int ntiles, int nblocks)
{
    extern __shared__ float sm[];
    float* smBl   = sm + SM_BL;
    int*   smConn = (int*)(sm + SM_CONN);

    int tid = threadIdx.x;

    if (tid < NB) {
        smBl[tid] = bl[tid];
        smConn[2 * tid]     = (int)conn[2 * tid];
        smConn[2 * tid + 1] = (int)conn[2 * tid + 1];
    }

    // M = K @ R^T
    const float f = 525.0f, cx = 320.0f, cy = 240.0f;
    float M00 = f*R[0] + cx*R[2];
    float M01 = f*R[3] + cx*R[5];
    float M02 = f*R[6] + cx*R[8];
    float M10 = f*R[1] + cy*R[2];
    float M11 = f*R[4] + cy*R[5];
    float M12 = f*R[7] + cy*R[8];
    float M20 = R[2], M21 = R[5], M22 = R[8];
    float Cx = C[0], Cy = C[1], Cz = C[2];

    unsigned int smemBase = (unsigned int)__cvta_generic_to_shared(sm);

    #define PREFETCH(tileIdx, bufIdx)                                          \
    do {                                                                       \
        int _base = (tileIdx) * TILE;                                          \
        int _cnt  = min(TILE, n - _base);                                      \
        const char* _ps = (const char*)pose + (size_t)_base * POSE_B;          \
        const char* _es = (const char*)est  + (size_t)_base * EST_B;           \
        unsigned int _sp = smemBase + (bufIdx) * (BUF_F * 4);                  \
        unsigned int _se = _sp + TILE_POSE_F * 4;                              \
        int _pb = _cnt * POSE_B;                                               \
        int _eb = _cnt * EST_B;                                                \
        _Pragma("unroll 4")                                                    \
        for (int c = tid * 16; c < _pb; c += THREADS * 16)                     \
            cp16(_sp + c, _ps + c, min(16, _pb - c));                          \
        _Pragma("unroll 4")                                                    \
        for (int c = tid * 16; c < _eb; c += THREADS * 16)                     \
            cp16(_se + c, _es + c, min(16, _eb - c));                          \
    } while (0)

    double accP = 0.0, accB = 0.0;

    int s_local = tid >> 1;       // sample within tile (0..63)
    int half    = tid & 1;        // 0: joints 0..10 / bones 0..9; 1: rest
    int j0      = half * 11;      // first joint for this lane (11 or 10 joints)
    int njl     = 11 - half;
    int b0      = half * 10;      // first bone (10 each)

    int t0 = blockIdx.x;
    if (t0 < ntiles) { PREFETCH(t0, 0); }
    cp_commit();

    int k = 0;
    for (int t = t0; t < ntiles; t += gridDim.x, k++) {
        int tn = t + gridDim.x;
        if (tn < ntiles) { PREFETCH(tn, (k + 1) & 1); }
        cp_commit();
        cp_wait1();
        __syncthreads();

        int base = t * TILE;
        int cnt  = min(TILE, n - base);
        const float* buf = sm + (k & 1) * BUF_F;

        if (s_local < cnt) {
            const float* P = buf + s_local * POSE_F;
            const float* E = buf + TILE_POSE_F + s_local * EST_F;

            float psum = 0.0f;
            #pragma unroll
            for (int i = 0; i < 11; i++) {
                if (i < njl) {
                    int j = j0 + i;
                    float dx = P[j]        - Cx;
                    float dy = P[NJ + j]   - Cy;
                    float dz = P[2*NJ + j] - Cz;
                    float px = M00*dx + M01*dy + M02*dz;
                    float py = M10*dx + M11*dy + M12*dz;
                    float pz = M20*dx + M21*dy + M22*dz;
                    float inv = __fdividef(1.0f, pz);
                    float u = px * inv - E[j];
                    float v = py * inv - E[NJ + j];
                    psum += u*u + v*v;
                }
            }

            float bsum = 0.0f;
            #pragma unroll
            for (int i = 0; i < 10; i++) {
                int jb = b0 + i;
                int a = smConn[2*jb];
                int b = smConn[2*jb + 1];
                float dx = P[a]        - P[b];
                float dy = P[NJ + a]   - P[NJ + b];
                float dz = P[2*NJ + a] - P[2*NJ + b];
                float sq = dx*dx + dy*dy + dz*dz;
                float tt = smBl[jb] - sq;
                bsum += tt*tt;
            }

            accP += (double)psum;
            accB += (double)bsum;
        }

        __syncthreads();   // compute done before buffer (k&1) is re-prefetched
    }
    cp_wait0();

    // block reduce
    #pragma unroll
    for (int o = 16; o > 0; o >>= 1) {
        accP += __shfl_down_sync(0xffffffffu, accP, o);
        accB += __shfl_down_sync(0xffffffffu, accB, o);
    }
    __shared__ double sP[4], sB[4];
    __shared__ bool isLast;
    int lane = tid & 31, wid = tid >> 5;
    if (lane == 0) { sP[wid] = accP; sB[wid] = accB; }
    __syncthreads();
    if (tid == 0) {
        double aP = sP[0] + sP[1] + sP[2] + sP[3];
        double aB = sB[0] + sB[1] + sB[2] + sB[3];
        g_partP[blockIdx.x] = aP;
        g_partB[blockIdx.x] = aB;
        __threadfence();
        unsigned int tk = atomicAdd(&g_ticket, 1u);
        isLast = (tk == (unsigned int)(nblocks - 1));
    }
    __syncthreads();

    if (isLast) {
        double aP = 0.0, aB = 0.0;
        for (int i = tid; i < nblocks; i += THREADS) {
            aP += g_partP[i];
            aB += g_partB[i];
        }
        #pragma unroll
        for (int o = 16; o > 0; o >>= 1) {
            aP += __shfl_down_sync(0xffffffffu, aP, o);
            aB += __shfl_down_sync(0xffffffffu, aB, o);
        }
        if (lane == 0) { sP[wid] = aP; sB[wid] = aB; }
        __syncthreads();
        if (tid == 0) {
            aP = sP[0] + sP[1] + sP[2] + sP[3];
            aB = sB[0] + sB[1] + sB[2] + sB[3];
            double invB = 1.0 / (double)n;
            double proj = aP * invB / (2.0 * NJ);
            double bone = aB * invB / (double)NB;
            out[0] = (float)(0.33 * proj + 0.5 * bone);
            g_ticket = 0;   // reset for next graph replay
        }
    }
}

extern "C" void kernel_launch(void* const* d_in, const int* in_sizes, int n_in,
                              void* d_out, int out_size) {
    const float*     pose = (const float*)d_in[0];
    const float*     est  = (const float*)d_in[1];
    const float*     bl   = (const float*)d_in[2];
    const float*     R    = (const float*)d_in[3];
    const float*     C    = (const float*)d_in[4];
    const long long* conn = (const long long*)d_in[5];
    float* out = (float*)d_out;

    int n = in_sizes[0] / (3 * NJ);
    int ntiles = (n + TILE - 1) / TILE;
    int blocks = 4 * 148;                // 4 blocks/SM, 54KB double buffer each
    if (blocks > ntiles) blocks = ntiles;
    if (blocks > MAXBLK) blocks = MAXBLK;

    cudaFuncSetAttribute(k_loss, cudaFuncAttributeMaxDynamicSharedMemorySize,
                         SMEM_BYTES);
    k_loss<<<blocks, THREADS, SMEM_BYTES>>>(pose, est, bl, R, C, conn, out,
                                            n, ntiles, blocks);
}

// round 6
// speedup vs baseline: 1.1204x; 1.1204x over previous
#include <cuda_runtime.h>

// pose3d_future loss — TILE=64 / 64-thread blocks / single cp.async buffer,
// 8 blocks per SM: many small dephased load/compute phase-machines keep DRAM
// continuously busy. One sample per thread, no predication on full tiles.
// P: [B,3,21] f32, E: [B,2,21] f32, bl: [20], R: [3,3], C: [3,1], conn: [20,2] i64

#define NJ 21
#define NB 20
#define TILE 64
#define THREADS 64
#define MAXBLK 2048

#define POSE_F 63
#define EST_F  42
#define POSE_B (POSE_F * 4)                 // 252
#define EST_B  (EST_F * 4)                  // 168
#define TILE_POSE_F (TILE * POSE_F)         // 4032
#define TILE_EST_F  (TILE * EST_F)          // 2688
#define BUF_F (TILE_POSE_F + TILE_EST_F)    // 6720 floats = 26880 B
#define SM_BL   BUF_F
#define SM_CONN (SM_BL + NB)
#define SM_FLOATS (SM_CONN + 2 * NB)
#define SMEM_BYTES (SM_FLOATS * 4)          // ~27.1 KB -> 8 blocks/SM

__device__ double g_partP[MAXBLK];
__device__ double g_partB[MAXBLK];
__device__ unsigned int g_ticket;

__device__ __forceinline__ void cp16(unsigned int dst, const void* src) {
    asm volatile("cp.async.cg.shared.global [%0], [%1], 16;\n"
                 :: "r"(dst), "l"(src));
}
__device__ __forceinline__ void cp_commit() {
    asm volatile("cp.async.commit_group;\n");
}
__device__ __forceinline__ void cp_wait0() {
    asm volatile("cp.async.wait_group 0;\n");
}

__global__ __launch_bounds__(THREADS) void k_loss(
    const float* __restrict__ pose,
    const float* __restrict__ est,
    const float* __restrict__ bl,
    const float* __restrict__ R,
    const float* __restrict__ C,
    const long long* __restrict__ conn,
    float* __restrict__ out,
    int n, int ntiles, int nblocks)
{
    extern __shared__ float sm[];
    float* smBl   = sm + SM_BL;
    int*   smConn = (int*)(sm + SM_CONN);

    int tid = threadIdx.x;

    if (tid < NB) {
        smBl[tid] = bl[tid];
        smConn[2 * tid]     = (int)conn[2 * tid];
        smConn[2 * tid + 1] = (int)conn[2 * tid + 1];
    }

    // M = K @ R^T
    const float f = 525.0f, cx = 320.0f, cy = 240.0f;
    float M00 = f*R[0] + cx*R[2];
    float M01 = f*R[3] + cx*R[5];
    float M02 = f*R[6] + cx*R[8];
    float M10 = f*R[1] + cy*R[2];
    float M11 = f*R[4] + cy*R[5];
    float M12 = f*R[7] + cy*R[8];
    float M20 = R[2], M21 = R[5], M22 = R[8];
    float Cx = C[0], Cy = C[1], Cz = C[2];

    unsigned int smemBase = (unsigned int)__cvta_generic_to_shared(sm);
    unsigned int seBase = smemBase + TILE_POSE_F * 4;

    double accP = 0.0, accB = 0.0;

    for (int t = blockIdx.x; t < ntiles; t += gridDim.x) {
        int base = t * TILE;
        int cnt  = min(TILE, n - base);

        __syncthreads();    // previous tile's compute fully done

        if (cnt == TILE) {
            // tile byte counts are multiples of 16: pose 16128B, est 10752B
            const char* ps = (const char*)pose + (size_t)base * POSE_B;
            const char* es = (const char*)est  + (size_t)base * EST_B;
            #pragma unroll 4
            for (int c = tid * 16; c < TILE * POSE_B; c += THREADS * 16)
                cp16(smemBase + c, ps + c);
            #pragma unroll 4
            for (int c = tid * 16; c < TILE * EST_B; c += THREADS * 16)
                cp16(seBase + c, es + c);
            cp_commit();
            cp_wait0();
        } else {
            for (int i = tid; i < cnt * POSE_F; i += THREADS)
                sm[i] = pose[(size_t)base * POSE_F + i];
            for (int i = tid; i < cnt * EST_F; i += THREADS)
                sm[TILE_POSE_F + i] = est[(size_t)base * EST_F + i];
        }
        __syncthreads();

        if (tid < cnt) {
            const float* P = sm + tid * POSE_F;
            const float* E = sm + TILE_POSE_F + tid * EST_F;

            float psum = 0.0f;
            #pragma unroll
            for (int j = 0; j < NJ; j++) {
                float dx = P[j]        - Cx;
                float dy = P[NJ + j]   - Cy;
                float dz = P[2*NJ + j] - Cz;
                float px = M00*dx + M01*dy + M02*dz;
                float py = M10*dx + M11*dy + M12*dz;
                float pz = M20*dx + M21*dy + M22*dz;
                float inv = __fdividef(1.0f, pz);
                float u = px * inv - E[j];
                float v = py * inv - E[NJ + j];
                psum += u*u + v*v;
            }

            float bsum = 0.0f;
            #pragma unroll
            for (int j = 0; j < NB; j++) {
                int a = smConn[2*j];
                int b = smConn[2*j + 1];
                float dx = P[a]        - P[b];
                float dy = P[NJ + a]   - P[NJ + b];
                float dz = P[2*NJ + a] - P[2*NJ + b];
                float sq = dx*dx + dy*dy + dz*dz;
                float tt = smBl[j] - sq;
                bsum += tt*tt;
            }

            accP += (double)psum;
            accB += (double)bsum;
        }
    }

    // block reduce (2 warps)
    #pragma unroll
    for (int o = 16; o > 0; o >>= 1) {
        accP += __shfl_down_sync(0xffffffffu, accP, o);
        accB += __shfl_down_sync(0xffffffffu, accB, o);
    }
    __shared__ double sP[2], sB[2];
    __shared__ bool isLast;
    int lane = tid & 31, wid = tid >> 5;
    if (lane == 0) { sP[wid] = accP; sB[wid] = accB; }
    __syncthreads();
    if (tid == 0) {
        double aP = sP[0] + sP[1];
        double aB = sB[0] + sB[1];
        g_partP[blockIdx.x] = aP;
        g_partB[blockIdx.x] = aB;
        __threadfence();
        unsigned int tk = atomicAdd(&g_ticket, 1u);
        isLast = (tk == (unsigned int)(nblocks - 1));
    }
    __syncthreads();

    if (isLast) {
        double aP = 0.0, aB = 0.0;
        for (int i = tid; i < nblocks; i += THREADS) {
            aP += g_partP[i];
            aB += g_partB[i];
        }
        #pragma unroll
        for (int o = 16; o > 0; o >>= 1) {
            aP += __shfl_down_sync(0xffffffffu, aP, o);
            aB += __shfl_down_sync(0xffffffffu, aB, o);
        }
        if (lane == 0) { sP[wid] = aP; sB[wid] = aB; }
        __syncthreads();
        if (tid == 0) {
            aP = sP[0] + sP[1];
            aB = sB[0] + sB[1];
            double invB = 1.0 / (double)n;
            double proj = aP * invB / (2.0 * NJ);
            double bone = aB * invB / (double)NB;
            out[0] = (float)(0.33 * proj + 0.5 * bone);
            g_ticket = 0;   // reset for next graph replay
        }
    }
}

extern "C" void kernel_launch(void* const* d_in, const int* in_sizes, int n_in,
                              void* d_out, int out_size) {
    const float*     pose = (const float*)d_in[0];
    const float*     est  = (const float*)d_in[1];
    const float*     bl   = (const float*)d_in[2];
    const float*     R    = (const float*)d_in[3];
    const float*     C    = (const float*)d_in[4];
    const long long* conn = (const long long*)d_in[5];
    float* out = (float*)d_out;

    int n = in_sizes[0] / (3 * NJ);
    int ntiles = (n + TILE - 1) / TILE;
    int blocks = 8 * 148;               // 8 blocks/SM, 27KB buffer each
    if (blocks > ntiles) blocks = ntiles;
    if (blocks > MAXBLK) blocks = MAXBLK;

    cudaFuncSetAttribute(k_loss, cudaFuncAttributeMaxDynamicSharedMemorySize,
                         SMEM_BYTES);
    k_loss<<<blocks, THREADS, SMEM_BYTES>>>(pose, est, bl, R, C, conn, out,
                                            n, ntiles, blocks);
}